// round 17
// baseline (speedup 1.0000x reference)
#include <cuda_runtime.h>
#include <math.h>

#define NB 16
#define NH 32
#define NKVH 8
#define ND 128
#define NS 4096
#define NG 4
#define NSPLIT 32
#define CHUNK 128
#define TILE 128
// score domain = log2: q pre-scaled by (1/sqrt(128)) * log2(e)
#define QSCALE (0.08838834764831845f * 1.4426950408889634f)

typedef unsigned long long u64;

// Static device scratch (no allocation allowed). Zero-initialized at load.
__device__ float  g_acc[(size_t)NB * NH * NSPLIT * ND];  // 8.4 MB
__device__ float2 g_ml[NB * NH * NSPLIT];                // (m, l) packed

__device__ __forceinline__ float ex2(float x)
{
    float y;
    asm("ex2.approx.f32 %0, %1;" : "=f"(y) : "f"(x));
    return y;
}

// Packed f32x2 helpers (SASS FFMA2/FMUL2 via PTX f32x2 ops).
__device__ __forceinline__ u64 packdup(float x)
{
    unsigned xi = __float_as_uint(x);
    u64 r;
    asm("mov.b64 %0, {%1, %2};" : "=l"(r) : "r"(xi), "r"(xi));
    return r;
}
__device__ __forceinline__ u64 fma2(u64 a, u64 b, u64 c)
{
    u64 d;
    asm("fma.rn.f32x2 %0, %1, %2, %3;" : "=l"(d) : "l"(a), "l"(b), "l"(c));
    return d;
}
__device__ __forceinline__ u64 mul2(u64 a, u64 b)
{
    u64 d;
    asm("mul.rn.f32x2 %0, %1, %2;" : "=l"(d) : "l"(a), "l"(b));
    return d;
}

// Score for one key: RoPE(K) dot q for 4 heads; after the interleaved
// 6-shuffle reduction, lane l holds the COMPLETE score of head (l&3).
__device__ __forceinline__ float score_key(
    float4 cc, float2 kA, float2 kB, int lane,
    const float* qlx, const float* qly, const float* qhx, const float* qhy)
{
    float r0 = kA.x * cc.x - kB.x * cc.z;
    float r1 = kA.y * cc.y - kB.y * cc.w;
    float r2 = kB.x * cc.x + kA.x * cc.z;
    float r3 = kB.y * cc.y + kA.y * cc.w;

    float d0 = qlx[0] * r0 + qly[0] * r1 + qhx[0] * r2 + qhy[0] * r3;
    float d1 = qlx[1] * r0 + qly[1] * r1 + qhx[1] * r2 + qhy[1] * r3;
    float d2 = qlx[2] * r0 + qly[2] * r1 + qhx[2] * r2 + qhy[2] * r3;
    float d3 = qlx[3] * r0 + qly[3] * r1 + qhx[3] * r2 + qhy[3] * r3;

    float s1  = (lane & 1) ? d0 : d1;
    float e01 = ((lane & 1) ? d1 : d0) + __shfl_xor_sync(0xffffffffu, s1, 1);
    float s2  = (lane & 1) ? d2 : d3;
    float e23 = ((lane & 1) ? d3 : d2) + __shfl_xor_sync(0xffffffffu, s2, 1);
    float s3  = (lane & 2) ? e01 : e23;
    float f   = ((lane & 2) ? e23 : e01) + __shfl_xor_sync(0xffffffffu, s3, 2);
    f += __shfl_xor_sync(0xffffffffu, f, 4);
    f += __shfl_xor_sync(0xffffffffu, f, 8);
    f += __shfl_xor_sync(0xffffffffu, f, 16);
    return f;
}

// ---------------------------------------------------------------------------
// Main split-KV kernel. CTA = (split, batch); warp = kv head.
// Register double-buffered 4-key groups (UNCHANGED mainloop — best measured).
// ---------------------------------------------------------------------------
__global__ __launch_bounds__(256, 2)
void pa_partial_kernel(const float* __restrict__ query,
                       const float* __restrict__ k_cache,
                       const float* __restrict__ v_cache,
                       const int*   __restrict__ slots,
                       const int*   __restrict__ positions,
                       const int*   __restrict__ ctx_lens)
{
    __shared__ float4 cs[TILE][32];   // rope factors: 64 KB
    __shared__ int    slot_sh[TILE];

    const int split = blockIdx.x;
    const int b     = blockIdx.y;
    const int tid   = threadIdx.x;
    const int w     = tid >> 5;       // warp = kv head
    const int lane  = tid & 31;

    const int ctx     = ctx_lens[b];
    const int s_begin = split * CHUNK;

    if (s_begin >= ctx) return;       // empty split: combine zero-gates it
    const int n = min(ctx - s_begin, CHUNK);

    // inv_freq for this lane's pair — fp64, once per thread (noise-level cost).
    const float inv0 = (float)exp(-9.210340371976184 * (double)(2 * lane)     / 64.0);
    const float inv1 = (float)exp(-9.210340371976184 * (double)(2 * lane + 1) / 64.0);

    // ---- cooperative fill: slots + rope factors (sincos once per (b,s)) ----
    if (tid < n) slot_sh[tid] = slots[b * NS + s_begin + tid];
    for (int key = w; key < n; key += 8) {
        float p = (float)positions[b * NS + s_begin + key];
        float fs0, fc0, fs1, fc1;
        sincosf(p * inv0, &fs0, &fc0);
        sincosf(p * inv1, &fs1, &fc1);
        cs[key][lane] = make_float4(fc0, fc1, fs0, fs1);
    }

    // ---- RoPE'd + log2-scaled query (4 heads) in registers ----
    float qlx[NG], qly[NG], qhx[NG], qhy[NG];
    {
        const int pos_last = positions[b * NS + ctx - 1];
        float sn0, cn0, sn1, cn1;
        sincosf((float)pos_last * inv0, &sn0, &cn0);
        sincosf((float)pos_last * inv1, &sn1, &cn1);
#pragma unroll
        for (int g = 0; g < NG; g++) {
            const float* qp = query + (size_t)(b * NH + w * NG + g) * ND;
            float2 a  = *(const float2*)(qp + 2 * lane);
            float2 bb = *(const float2*)(qp + 2 * lane + 64);
            qlx[g] = (a.x * cn0 - bb.x * sn0) * QSCALE;
            qly[g] = (a.y * cn1 - bb.y * sn1) * QSCALE;
            qhx[g] = (bb.x * cn0 + a.x * sn0) * QSCALE;
            qhy[g] = (bb.y * cn1 + a.y * sn1) * QSCALE;
        }
    }

    // Distributed softmax state: lane l tracks m/l of head (l&3), log2 domain.
    float mL = -1e30f, lL = 0.f;
    u64 accA[NG], accB[NG];
#pragma unroll
    for (int g = 0; g < NG; g++) { accA[g] = 0ull; accB[g] = 0ull; }

    __syncthreads();

    const float* kb = k_cache + w * ND;
    const float* vb = v_cache + w * ND;

    float2 kA0[4], kB0[4], kA1[4], kB1[4];
    ulonglong2 v0[4], v1[4];           // V rows pre-packed as 2×f32x2

#define LOADG(KA, KB, VV, base)                                         \
    {                                                                   \
        _Pragma("unroll")                                               \
        for (int j = 0; j < 4; j++) {                                   \
            int sl_ = slot_sh[(base) + j];                              \
            const float* kr_ = kb + ((size_t)sl_ << 10);                \
            const float* vr_ = vb + ((size_t)sl_ << 10);                \
            KA[j] = *(const float2*)(kr_ + 2 * lane);                   \
            KB[j] = *(const float2*)(kr_ + 2 * lane + 64);              \
            VV[j] = *(const ulonglong2*)(vr_ + 4 * lane);               \
        }                                                               \
    }

#define LOADG_C(KA, KB, VV, base)                                       \
    {                                                                   \
        _Pragma("unroll")                                               \
        for (int j = 0; j < 4; j++) {                                   \
            int sl_ = slot_sh[min((base) + j, n - 1)];                  \
            const float* kr_ = kb + ((size_t)sl_ << 10);                \
            const float* vr_ = vb + ((size_t)sl_ << 10);                \
            KA[j] = *(const float2*)(kr_ + 2 * lane);                   \
            KB[j] = *(const float2*)(kr_ + 2 * lane + 64);              \
            VV[j] = *(const ulonglong2*)(vr_ + 4 * lane);               \
        }                                                               \
    }

#define PROCG(KA, KB, VV, base, MASKED)                                 \
    {                                                                   \
        float sc0 = score_key(cs[(base) + 0][lane], KA[0], KB[0], lane, qlx, qly, qhx, qhy); \
        float sc1 = score_key(cs[(base) + 1 < TILE ? (base) + 1 : 0][lane], KA[1], KB[1], lane, qlx, qly, qhx, qhy); \
        float sc2 = score_key(cs[(base) + 2 < TILE ? (base) + 2 : 0][lane], KA[2], KB[2], lane, qlx, qly, qhx, qhy); \
        float sc3 = score_key(cs[(base) + 3 < TILE ? (base) + 3 : 0][lane], KA[3], KB[3], lane, qlx, qly, qhx, qhy); \
        if (MASKED) {                                                   \
            if ((base) + 1 >= n) sc1 = -1e30f;                          \
            if ((base) + 2 >= n) sc2 = -1e30f;                          \
            if ((base) + 3 >= n) sc3 = -1e30f;                          \
        }                                                               \
        float gmax = fmaxf(fmaxf(sc0, sc1), fmaxf(sc2, sc3));           \
        float mn   = fmaxf(mL, gmax);                                   \
        float corr = ex2(mL - mn);                                      \
        mL = mn;                                                        \
        lL *= corr;                                                     \
        {                                                               \
            u64 cp0 = packdup(__shfl_sync(0xffffffffu, corr, 0));       \
            u64 cp1 = packdup(__shfl_sync(0xffffffffu, corr, 1));       \
            u64 cp2 = packdup(__shfl_sync(0xffffffffu, corr, 2));       \
            u64 cp3 = packdup(__shfl_sync(0xffffffffu, corr, 3));       \
            accA[0] = mul2(accA[0], cp0); accB[0] = mul2(accB[0], cp0); \
            accA[1] = mul2(accA[1], cp1); accB[1] = mul2(accB[1], cp1); \
            accA[2] = mul2(accA[2], cp2); accB[2] = mul2(accB[2], cp2); \
            accA[3] = mul2(accA[3], cp3); accB[3] = mul2(accB[3], cp3); \
        }                                                               \
        _Pragma("unroll")                                               \
        for (int j = 0; j < 4; j++) {                                   \
            float scj = (j == 0) ? sc0 : (j == 1) ? sc1 : (j == 2) ? sc2 : sc3; \
            float wv2 = ex2(scj - mn);                                  \
            lL += wv2;                                                  \
            u64 w0 = packdup(__shfl_sync(0xffffffffu, wv2, 0));         \
            u64 w1 = packdup(__shfl_sync(0xffffffffu, wv2, 1));         \
            u64 w2 = packdup(__shfl_sync(0xffffffffu, wv2, 2));         \
            u64 w3 = packdup(__shfl_sync(0xffffffffu, wv2, 3));         \
            ulonglong2 vj = VV[j];                                      \
            accA[0] = fma2(w0, vj.x, accA[0]); accB[0] = fma2(w0, vj.y, accB[0]); \
            accA[1] = fma2(w1, vj.x, accA[1]); accB[1] = fma2(w1, vj.y, accB[1]); \
            accA[2] = fma2(w2, vj.x, accA[2]); accB[2] = fma2(w2, vj.y, accB[2]); \
            accA[3] = fma2(w3, vj.x, accA[3]); accB[3] = fma2(w3, vj.y, accB[3]); \
        }                                                               \
    }

    if (n == CHUNK) {
        // Clean path: 32 full groups, double-buffered, no clamps/masks.
        LOADG(kA0, kB0, v0, 0);
#pragma unroll 1
        for (int base = 0; base < CHUNK; base += 8) {
            LOADG(kA1, kB1, v1, base + 4);
            PROCG(kA0, kB0, v0, base, 0);
            if (base + 8 < CHUNK) LOADG(kA0, kB0, v0, base + 8);
            PROCG(kA1, kB1, v1, base + 4, 0);
        }
    } else {
        // Ragged path (<= 1 CTA per batch): clamped loads + masked scores.
        LOADG_C(kA0, kB0, v0, 0);
#pragma unroll 1
        for (int base = 0; base < n; base += 8) {
            if (base + 4 < n) LOADG_C(kA1, kB1, v1, base + 4);
            PROCG(kA0, kB0, v0, base, 1);
            if (base + 4 < n) {
                if (base + 8 < n) LOADG_C(kA0, kB0, v0, base + 8);
                PROCG(kA1, kB1, v1, base + 4, 1);
            }
        }
    }
#undef LOADG
#undef LOADG_C
#undef PROCG

    // ---- write split partials (m in log2 domain; acc stored packed) ----
#pragma unroll
    for (int g = 0; g < NG; g++) {
        size_t p = (size_t)(b * NH + w * NG + g) * NSPLIT + split;
        ulonglong2 st; st.x = accA[g]; st.y = accB[g];
        *(ulonglong2*)(g_acc + p * ND + 4 * lane) = st;
    }
    if (lane < NG) {
        size_t p = (size_t)(b * NH + w * NG + lane) * NSPLIT + split;
        g_ml[p] = make_float2(mL, lL);
    }
}

// ---------------------------------------------------------------------------
// Combine: 512 blocks x 128 threads, warp-autonomous (ZERO barriers).
// Launched with PDL: blocks spin up DURING the partial kernel; the
// griddepcontrol.wait gates all reads of g_acc/g_ml on partial completion.
// ---------------------------------------------------------------------------
__global__ __launch_bounds__(128)
void pa_combine_kernel(float* __restrict__ out, const int* __restrict__ ctx_lens)
{
    const int bh   = blockIdx.x;         // b*NH + h
    const int tid  = threadIdx.x;        // 0..127 == output dim d
    const int lane = tid & 31;

    const int ctx  = ctx_lens[bh >> 5];  // input, not produced by partial
    const int nact = (ctx + CHUNK - 1) >> 7;   // active splits, >=1

    // Wait for the partial kernel's completion (PDL gate) before touching
    // g_ml / g_acc. Launch+ramp happened concurrently with the partial.
    cudaGridDependencySynchronize();

    // lane s holds (m,l) of split s; inactive lanes masked.
    float2 ml = g_ml[bh * NSPLIT + lane];
    float mv = (lane < nact) ? ml.x : -1e30f;
    float lv = (lane < nact) ? ml.y : 0.f;

    // Warp max of m.
    float M = mv;
#pragma unroll
    for (int o = 16; o > 0; o >>= 1)
        M = fmaxf(M, __shfl_xor_sync(0xffffffffu, M, o));

    float wv = ex2(mv - M);              // exactly 0 for inactive lanes
    float Lp = wv * lv;
#pragma unroll
    for (int o = 16; o > 0; o >>= 1)
        Lp += __shfl_xor_sync(0xffffffffu, Lp, o);

    // 32 independent, unconditional loads (full MLP); weights via shuffle.
    const float* ap = g_acc + (size_t)bh * NSPLIT * ND + tid;
    float o = 0.f;
#pragma unroll
    for (int s = 0; s < NSPLIT; s++) {
        float ws = __shfl_sync(0xffffffffu, wv, s);
        o += ws * ap[s * ND];
    }
    out[(size_t)bh * ND + tid] = o / Lp;
}

extern "C" void kernel_launch(void* const* d_in, const int* in_sizes, int n_in,
                              void* d_out, int out_size)
{
    const float* query     = (const float*)d_in[0];
    const float* k_cache   = (const float*)d_in[1];
    const float* v_cache   = (const float*)d_in[2];
    const int*   slots     = (const int*)d_in[3];
    const int*   positions = (const int*)d_in[4];
    const int*   ctx_lens  = (const int*)d_in[5];
    float*       out       = (float*)d_out;

    dim3 grid(NSPLIT, NB);
    pa_partial_kernel<<<grid, 256>>>(query, k_cache, v_cache,
                                     slots, positions, ctx_lens);

    // PDL launch: combine spins up while the partial is still running; its
    // cudaGridDependencySynchronize() enforces the data dependency.
    cudaLaunchConfig_t cfg = {};
    cfg.gridDim  = dim3(NB * NH, 1, 1);
    cfg.blockDim = dim3(128, 1, 1);
    cudaLaunchAttribute attrs[1];
    attrs[0].id = cudaLaunchAttributeProgrammaticStreamSerialization;
    attrs[0].val.programmaticStreamSerializationAllowed = 1;
    cfg.attrs    = attrs;
    cfg.numAttrs = 1;
    cudaLaunchKernelEx(&cfg, pa_combine_kernel, out, ctx_lens);
}